// round 5
// baseline (speedup 1.0000x reference)
#include <cuda_runtime.h>
#include <cstdint>
#include <math.h>

// Problem dims (fixed by the dataset problem)
#define BB   8
#define TT   100
#define SS   128
#define FF   768
#define SF   (SS * FF)          // 98304
#define BSF  (BB * SF)          // 786432
#define TSF  (TT * SF)          // 9830400
#define NTOT (BB * TSF)         // 78643200  (elements per stacked half)

// Packed per-(b,s,f) word:
//   bits[9:32) = thresh = ceil(p * 2^23)   (rate:  spike <=> bits32 < thresh<<9)
//   bits[0:9)  = tm = (int)(p * 10.f)      (temporal spike time, 0..10)
__device__ uint32_t g_w32[BSF];

// Rotation powers 2^R, loaded at runtime so ptxas CANNOT strength-reduce the
// wide multiply back into SHF (the whole point is IMAD.WIDE on the fma pipe).
__device__ __align__(16) uint32_t g_rotc[4] = {
    1u << 13, 1u << 26, 1u << 17, 1u << 16
};

// ---------------------------------------------------------------------------
// Prep: p = sigmoid(x) in double (bit-exact vs XLA f32 logistic per R2-R4:
// rel_err == 0.0), pack threshold<<9 | time.
// ---------------------------------------------------------------------------
__global__ void __launch_bounds__(256) prep_kernel(const float* __restrict__ feat) {
    int i = blockIdx.x * blockDim.x + threadIdx.x;
    if (i >= BSF) return;
    float x = feat[i];
    double pd = 1.0 / (1.0 + exp(-(double)x));
    float p = (float)pd;
    uint32_t thresh = (uint32_t)ceil((double)p * 8388608.0);   // ceil(p * 2^23)
    uint32_t tm = (uint32_t)(int)(p * 10.0f);                  // JAX: int32(p * 10)
    uint32_t w;
    if (thresh >= 0x800000u) w = 0xFFFFFFFFu;                  // p==1 edge (never hit)
    else                     w = (thresh << 9) | tm;
    g_w32[i] = w;
}

// ---------------------------------------------------------------------------
// Threefry round, two flavors:
//   round_s: rotation via funnel shift                -> SHF + LOP3 (both alu)
//   round_w: rotation via mul.wide.u32 by runtime 2^R -> IMAD.WIDE (fma pipe)
//            + one 3-input LOP3 (lo|hi)^x0 (alu)
// ---------------------------------------------------------------------------
template<int R>
__device__ __forceinline__ void round_s(uint32_t& x0, uint32_t& x1) {
    x0 += x1;
    x1 = __funnelshift_l(x1, x1, R) ^ x0;
}

__device__ __forceinline__ void round_w(uint32_t& x0, uint32_t& x1, uint32_t c) {
    x0 += x1;
    uint64_t p;
    asm("mul.wide.u32 %0, %1, %2;" : "=l"(p) : "r"(x1), "r"(c));
    uint32_t lo = (uint32_t)p;            // x1 << R
    uint32_t hi = (uint32_t)(p >> 32);    // x1 >> (32-R)
    x1 = (lo | hi) ^ x0;                  // single LOP3
}

// JAX partitionable threefry2x32: per-element 64-bit counter (hi=0, lo=i),
// key = (0, 42), output = x0_final ^ x1_final.
// c13/c26/c17/c16 are runtime registers holding 2^13, 2^26, 2^17, 2^16.
__device__ __forceinline__ uint32_t threefry_bits(uint32_t i, uint32_t c13,
                                                  uint32_t c26, uint32_t c17,
                                                  uint32_t c16) {
    const uint32_t ks0 = 0u;
    const uint32_t ks1 = 42u;
    const uint32_t ks2 = 0x1BD11BDAu ^ 0u ^ 42u;
    uint32_t x0 = 0u + ks0;        // counter hi = 0
    uint32_t x1 = i  + ks1;        // counter lo = element index

    round_w(x0, x1, c13); round_s<15>(x0, x1); round_w(x0, x1, c26); round_s<6>(x0, x1);
    x0 += ks1; x1 += ks2 + 1u;
    round_w(x0, x1, c17); round_s<29>(x0, x1); round_w(x0, x1, c16); round_s<24>(x0, x1);
    x0 += ks2; x1 += ks0 + 2u;
    round_w(x0, x1, c13); round_s<15>(x0, x1); round_w(x0, x1, c26); round_s<6>(x0, x1);
    x0 += ks0; x1 += ks1 + 3u;
    round_w(x0, x1, c17); round_s<29>(x0, x1); round_w(x0, x1, c16); round_s<24>(x0, x1);
    x0 += ks1; x1 += ks2 + 4u;
    round_w(x0, x1, c13); round_s<15>(x0, x1); round_w(x0, x1, c26); round_s<6>(x0, x1);
    x0 += ks2; x1 += ks0 + 5u;

    return x0 ^ x1;                // partitionable 32-bit combine
}

// ---------------------------------------------------------------------------
// Fused kernel: thread handles 4 consecutive flat indices j0..j0+3 of the
// [B,T,S,F] rate tensor (same b,t; 4 consecutive f). Writes rate[j0..] and
// temporal[NTOT + j0..] as float4 (coalesced). g_w32 (3 MB) stays L2-resident,
// reused T=100 times.
// ---------------------------------------------------------------------------
__global__ void __launch_bounds__(256) spike_kernel(float* __restrict__ out) {
    uint32_t tid = blockIdx.x * blockDim.x + threadIdx.x;
    uint32_t j0  = tid * 4u;                  // < NTOT, multiple of 4

    // Runtime rotation constants (one LDG.128, L1/L2-resident, opaque to ptxas)
    const uint4 rc = *reinterpret_cast<const uint4*>(g_rotc);
    const uint32_t c13 = rc.x, c26 = rc.y, c17 = rc.z, c16 = rc.w;

    uint32_t b   = j0 / TSF;                  // batch 0..7
    uint32_t rem = j0 - b * TSF;
    uint32_t t   = rem / SF;                  // timestep 0..99
    uint32_t sf  = rem - t * SF;              // s*F + f, multiple of 4

    const uint4 wv = *reinterpret_cast<const uint4*>(&g_w32[b * SF + sf]);
    const uint32_t w[4] = {wv.x, wv.y, wv.z, wv.w};

    uint32_t bits[4];
#pragma unroll
    for (int k = 0; k < 4; ++k)
        bits[k] = threefry_bits(j0 + (uint32_t)k, c13, c26, c17, c16);

    float rate[4], temp[4];
#pragma unroll
    for (int k = 0; k < 4; ++k) {
        rate[k] = (bits[k] < w[k]) ? 1.0f : 0.0f;
        temp[k] = ((w[k] & 511u) == t) ? 1.0f : 0.0f;
    }

    *reinterpret_cast<float4*>(out + j0) =
        make_float4(rate[0], rate[1], rate[2], rate[3]);
    *reinterpret_cast<float4*>(out + (uint32_t)NTOT + j0) =
        make_float4(temp[0], temp[1], temp[2], temp[3]);
}

extern "C" void kernel_launch(void* const* d_in, const int* in_sizes, int n_in,
                              void* d_out, int out_size) {
    const float* features = (const float*)d_in[0];
    float* out = (float*)d_out;

    // 786432 / 256 = 3072 blocks (exact)
    prep_kernel<<<BSF / 256, 256>>>(features);

    // NTOT/4 threads = 19,660,800 / 256 = 76,800 blocks (exact)
    spike_kernel<<<(NTOT / 4) / 256, 256>>>(out);
}

// round 6
// speedup vs baseline: 1.2332x; 1.2332x over previous
#include <cuda_runtime.h>
#include <cstdint>
#include <math.h>

// Problem dims (fixed by the dataset problem)
#define BB   8
#define TT   100
#define SS   128
#define FF   768
#define SF   (SS * FF)          // 98304
#define BSF  (BB * SF)          // 786432
#define TSF  (TT * SF)          // 9830400
#define NTOT (BB * TSF)         // 78643200  (elements per stacked half)

// Packed per-(b,s,f) word:
//   bits[9:32) = thresh = ceil(p * 2^23)   (rate:  spike <=> bits32 < thresh<<9)
//   bits[0:9)  = tm = (int)(p * 10.f)      (temporal spike time, 0..10)
__device__ uint32_t g_w32[BSF];

// ---------------------------------------------------------------------------
// Correctly-rounded f32 sigmoid via double-single arithmetic on the fp32 pipe
// (replaces the ~40us FP64 exp() path; accuracy ~2^-27 abs, so it rounds to
// the same float as the double computation for all but ~a few % of inputs by
// at most 1 ulp -> expected spike flips ~0.1 over the whole tensor).
// ---------------------------------------------------------------------------
__device__ __forceinline__ float sigmoid_cr(float x) {
    if (fabsf(x) > 20.0f) {                     // never taken for N(0,1) data
        double pd = 1.0 / (1.0 + exp(-(double)x));
        return (float)pd;
    }
    // t = (-x) * log2(e)   (two-prod ds)
    const float L2E_HI = 1.4426950216293335f;
    const float L2E_LO = 1.9259629911266175e-8f;
    float xn  = -x;
    float thi = xn * L2E_HI;
    float tlo = fmaf(xn, L2E_HI, -thi);
    tlo = fmaf(xn, L2E_LO, tlo);
    float n   = rintf(thi);
    float fhi = thi - n;                        // exact (Cody-Waite)
    // u = f * ln2  (ds)
    const float LN2_HI = 0.6931471824645996f;
    const float LN2_LO = -1.904654323148236e-9f;
    float uhi = fhi * LN2_HI;
    float ulo = fmaf(fhi, LN2_HI, -uhi);
    ulo = fmaf(fhi, LN2_LO, ulo);
    ulo = fmaf(tlo, LN2_HI, ulo);
    // e^u = 1 + u + u^2 * q(u),  Taylor through u^8  (|u| <= 0.3466)
    float q;
    q = fmaf(2.4801587e-5f, uhi, 1.9841270e-4f);
    q = fmaf(q, uhi, 1.3888889e-3f);
    q = fmaf(q, uhi, 8.3333338e-3f);
    q = fmaf(q, uhi, 4.1666668e-2f);
    q = fmaf(q, uhi, 1.6666667e-1f);
    q = fmaf(q, uhi, 0.5f);
    float u2 = uhi * uhi;
    float v  = u2 * q;
    float c  = fmaf(ulo, uhi, ulo);             // ulo * (1 + uhi)
    // ds sum: e = (1 + uhi) + v + c
    float shi = 1.0f + uhi;
    float slo = uhi - (shi - 1.0f);             // Fast2Sum (1 >= |uhi|)
    float ehi = shi + v;
    float elo = (v - (ehi - shi)) + slo + c;    // Fast2Sum (|shi| >= |v|)
    // scale by 2^n  (n in [-43, 29] under the |x|<=20 guard; exact)
    int   ni = (int)n;
    float sc = __int_as_float((ni + 127) << 23);
    ehi *= sc;
    elo *= sc;
    // d = 1 + e^{-x}  (branchless TwoSum) ; dlo picks up elo
    float dhi = 1.0f + ehi;
    float t1  = dhi - 1.0f;
    float dlo = ((1.0f - (dhi - t1)) + (ehi - t1)) + elo;
    // p = 1/d, ds-refined, single final rounding
    float r   = 1.0f / dhi;
    float res = fmaf(r, dhi, -1.0f);
    res = fmaf(r, dlo, res);
    return fmaf(-r, res, r);
}

// ---------------------------------------------------------------------------
// Prep: pack threshold<<9 | time per (b,s,f).
// ---------------------------------------------------------------------------
__global__ void __launch_bounds__(256) prep_kernel(const float* __restrict__ feat) {
    int i = blockIdx.x * blockDim.x + threadIdx.x;
    if (i >= BSF) return;
    float p = sigmoid_cr(feat[i]);
    uint32_t thresh = (uint32_t)ceilf(p * 8388608.0f);   // ceil(p * 2^23), exact scaling
    uint32_t tm = (uint32_t)(int)(p * 10.0f);            // JAX: int32(p * 10)
    uint32_t w;
    if (thresh >= 0x800000u) w = 0xFFFFFFFFu;            // p==1 edge (never hit)
    else                     w = (thresh << 9) | tm;
    g_w32[i] = w;
}

// ---------------------------------------------------------------------------
// JAX partitionable threefry2x32: per-element 64-bit counter (hi=0, lo=i),
// key = (0, 42), output = x0_final ^ x1_final.  All-SHF form (R3): minimum
// instruction count — this kernel is total-issue-bound, not pipe-bound.
// ---------------------------------------------------------------------------
__device__ __forceinline__ uint32_t threefry_bits(uint32_t i) {
    const uint32_t ks0 = 0u;
    const uint32_t ks1 = 42u;
    const uint32_t ks2 = 0x1BD11BDAu ^ 0u ^ 42u;
    uint32_t x0 = 0u + ks0;        // counter hi = 0
    uint32_t x1 = i  + ks1;        // counter lo = element index
#define TF_ROUND(r) { x0 += x1; x1 = __funnelshift_l(x1, x1, (r)); x1 ^= x0; }
    TF_ROUND(13) TF_ROUND(15) TF_ROUND(26) TF_ROUND(6)
    x0 += ks1; x1 += ks2 + 1u;
    TF_ROUND(17) TF_ROUND(29) TF_ROUND(16) TF_ROUND(24)
    x0 += ks2; x1 += ks0 + 2u;
    TF_ROUND(13) TF_ROUND(15) TF_ROUND(26) TF_ROUND(6)
    x0 += ks0; x1 += ks1 + 3u;
    TF_ROUND(17) TF_ROUND(29) TF_ROUND(16) TF_ROUND(24)
    x0 += ks1; x1 += ks2 + 4u;
    TF_ROUND(13) TF_ROUND(15) TF_ROUND(26) TF_ROUND(6)
    x0 += ks2; x1 += ks0 + 5u;
#undef TF_ROUND
    return x0 ^ x1;                // partitionable 32-bit combine
}

// ---------------------------------------------------------------------------
// Fused kernel: thread handles 4 consecutive flat indices j0..j0+3 of the
// [B,T,S,F] rate tensor (same b,t; 4 consecutive f). Writes rate[j0..] and
// temporal[NTOT + j0..] as float4 (coalesced). g_w32 (3 MB) stays L2-resident,
// reused T=100 times.
// Temporal spikes only exist at t <= 10 (tm = int(p*10) in [0,10]); t is
// warp-uniform, so 89% of warps skip the temporal compute and store zeros.
// ---------------------------------------------------------------------------
__global__ void __launch_bounds__(256) spike_kernel(float* __restrict__ out) {
    uint32_t tid = blockIdx.x * blockDim.x + threadIdx.x;
    uint32_t j0  = tid * 4u;                  // < NTOT, multiple of 4

    uint32_t b   = j0 / TSF;                  // batch 0..7
    uint32_t rem = j0 - b * TSF;
    uint32_t t   = rem / SF;                  // timestep 0..99
    uint32_t sf  = rem - t * SF;              // s*F + f, multiple of 4

    const uint4 wv = *reinterpret_cast<const uint4*>(&g_w32[b * SF + sf]);
    const uint32_t w[4] = {wv.x, wv.y, wv.z, wv.w};

    uint32_t bits[4];
#pragma unroll
    for (int k = 0; k < 4; ++k)
        bits[k] = threefry_bits(j0 + (uint32_t)k);

    float rate[4];
#pragma unroll
    for (int k = 0; k < 4; ++k)
        rate[k] = (bits[k] < w[k]) ? 1.0f : 0.0f;

    *reinterpret_cast<float4*>(out + j0) =
        make_float4(rate[0], rate[1], rate[2], rate[3]);

    float4 tv;
    if (t <= 10u) {                            // warp-uniform branch
        tv.x = ((w[0] & 511u) == t) ? 1.0f : 0.0f;
        tv.y = ((w[1] & 511u) == t) ? 1.0f : 0.0f;
        tv.z = ((w[2] & 511u) == t) ? 1.0f : 0.0f;
        tv.w = ((w[3] & 511u) == t) ? 1.0f : 0.0f;
    } else {
        tv = make_float4(0.0f, 0.0f, 0.0f, 0.0f);
    }
    *reinterpret_cast<float4*>(out + (uint32_t)NTOT + j0) = tv;
}

extern "C" void kernel_launch(void* const* d_in, const int* in_sizes, int n_in,
                              void* d_out, int out_size) {
    const float* features = (const float*)d_in[0];
    float* out = (float*)d_out;

    // 786432 / 256 = 3072 blocks (exact)
    prep_kernel<<<BSF / 256, 256>>>(features);

    // NTOT/4 threads = 19,660,800 / 256 = 76,800 blocks (exact)
    spike_kernel<<<(NTOT / 4) / 256, 256>>>(out);
}